// round 4
// baseline (speedup 1.0000x reference)
#include <cuda_runtime.h>
#include <stdint.h>
#include <math_constants.h>

// GraphPoolOut: voxel max-pool (bucket + gather, MLP-8 gather)
//   vertices: [N=1e6, 3] int32, values in [0,256)
//   features: [N, 64] float32
//   out: [64^3, 64] float32 flat; empty voxels -> 0
//
// R3 post-mortem: dynamic-trip-count gather loop had MLP=1 -> latency-bound
// ~120us. This version front-batches up to 8 independent feature loads per
// warp before reducing (uniform predicates; ptxas hoists the LDGs).

#define GP_GRID   64
#define GP_NVOX   (GP_GRID * GP_GRID * GP_GRID)   // 262144
#define GP_C      64
#define GP_CAP    32   // max points per voxel (Poisson(3.81): P(>31) ~ 1e-12)
#define GP_MLP    8    // front-batched loads; P(cnt>8) ~ 1.5%

// scratch (static device memory; no allocation APIs)
__device__ unsigned int g_cnt[GP_NVOX];             // 1 MB
__device__ int          g_bucket[GP_NVOX * GP_CAP]; // 32 MB

// ---- kernel 0: zero counters ----------------------------------------------
__global__ void gp_zero_cnt(void) {
    int i = blockIdx.x * blockDim.x + threadIdx.x;  // 262144 threads
    g_cnt[i] = 0u;
}

// ---- kernel 1: build per-voxel buckets ------------------------------------
__global__ void gp_build(const int* __restrict__ verts, int n_pts) {
    int i = blockIdx.x * blockDim.x + threadIdx.x;
    if (i >= n_pts) return;
    int v0 = verts[3 * i + 0] >> 2;                 // coords in [0,256): >>2 == //4
    int v1 = verts[3 * i + 1] >> 2;
    int v2 = verts[3 * i + 2] >> 2;
    int vox = (v0 << 12) | (v1 << 6) | v2;
    unsigned int pos = atomicAdd(&g_cnt[vox], 1u);
    if (pos < GP_CAP)
        g_bucket[(size_t)vox * GP_CAP + pos] = i;
}

// ---- kernel 2: warp-per-voxel gather max, 8 loads in flight ----------------
__global__ void gp_gather(const float2* __restrict__ feats,
                          float2*       __restrict__ out) {
    int vox  = (int)((blockIdx.x * (long long)blockDim.x + threadIdx.x) >> 5);
    int lane = threadIdx.x & 31;
    if (vox >= GP_NVOX) return;

    unsigned int cnt = g_cnt[vox];                  // warp-uniform
    if (cnt > GP_CAP) cnt = GP_CAP;

    // one coalesced 128B load pulls all bucket entries into lanes
    int myidx = 0;
    if (lane < (int)cnt)
        myidx = g_bucket[(size_t)vox * GP_CAP + lane];

    float2 acc;
    acc.x = -CUDART_INF_F;
    acc.y = -CUDART_INF_F;

    int m = (int)cnt;
    int head = (m < GP_MLP) ? m : GP_MLP;

    // front-batched independent loads (uniform guards -> ptxas hoists LDGs)
    float2 f[GP_MLP];
    #pragma unroll
    for (int k = 0; k < GP_MLP; ++k) {
        if (k < head) {
            int p = __shfl_sync(0xFFFFFFFFu, myidx, k);
            f[k] = feats[(size_t)p * 32 + lane];    // coalesced 256B per point
        }
    }
    #pragma unroll
    for (int k = 0; k < GP_MLP; ++k) {
        if (k < head) {
            acc.x = fmaxf(acc.x, f[k].x);
            acc.y = fmaxf(acc.y, f[k].y);
        }
    }

    // rare tail (P(cnt>8) ~ 1.5%)
    for (int j = GP_MLP; j < m; ++j) {
        int p = __shfl_sync(0xFFFFFFFFu, myidx, j);
        float2 t = feats[(size_t)p * 32 + lane];
        acc.x = fmaxf(acc.x, t.x);
        acc.y = fmaxf(acc.y, t.y);
    }

    if (m == 0) { acc.x = 0.0f; acc.y = 0.0f; }     // empty voxel -> zeros
    out[(size_t)vox * 32 + lane] = acc;             // coalesced 256B per voxel
}

extern "C" void kernel_launch(void* const* d_in, const int* in_sizes, int n_in,
                              void* d_out, int out_size) {
    const int*    verts = (const int*)d_in[0];      // [N,3] int32
    const float2* feats = (const float2*)d_in[1];   // [N,64] f32 viewed as [N,32] f2
    float2*       out   = (float2*)d_out;           // [NVOX*64] f32 viewed as f2

    int n_pts = in_sizes[0] / 3;                    // 1,000,000

    const int T = 256;

    // 0) zero counters
    gp_zero_cnt<<<GP_NVOX / T, T>>>();

    // 1) build buckets: thread per point
    gp_build<<<(n_pts + T - 1) / T, T>>>(verts, n_pts);

    // 2) gather: warp per voxel
    long long total_threads = (long long)GP_NVOX * 32;
    gp_gather<<<(int)((total_threads + T - 1) / T), T>>>(feats, out);
}

// round 5
// speedup vs baseline: 1.5362x; 1.5362x over previous
#include <cuda_runtime.h>
#include <stdint.h>
#include <math_constants.h>

// GraphPoolOut: voxel max-pool (bucket + gather, branch-free MLP-8 gather)
//   vertices: [N=1e6, 3] int32, values in [0,256)
//   features: [N, 64] float32
//   out: [64^3, 64] float32 flat; empty voxels -> 0
//
// R4 post-mortem: per-load `if` guards became BSSY/BSYNC regions (~35cyc each)
// -> regression. This version clamps indices instead: straight-line 8 shfls +
// 8 loads, duplicates merge in the L1tex pending-sector queue.

#define GP_GRID   64
#define GP_NVOX   (GP_GRID * GP_GRID * GP_GRID)   // 262144
#define GP_C      64
#define GP_CAP    32   // max points per voxel (Poisson(3.81): P(>31) ~ 1e-12)
#define GP_MLP    8    // straight-line batched loads; P(cnt>8) ~ 1.5%

// scratch (static device memory; no allocation APIs)
__device__ unsigned int g_cnt[GP_NVOX];             // 1 MB
__device__ int          g_bucket[GP_NVOX * GP_CAP]; // 32 MB

// ---- kernel 0: zero counters ----------------------------------------------
__global__ void gp_zero_cnt(void) {
    int i = blockIdx.x * blockDim.x + threadIdx.x;  // 262144 threads
    g_cnt[i] = 0u;
}

// ---- kernel 1: build per-voxel buckets ------------------------------------
__global__ void gp_build(const int* __restrict__ verts, int n_pts) {
    int i = blockIdx.x * blockDim.x + threadIdx.x;
    if (i >= n_pts) return;
    int v0 = verts[3 * i + 0] >> 2;                 // coords in [0,256): >>2 == //4
    int v1 = verts[3 * i + 1] >> 2;
    int v2 = verts[3 * i + 2] >> 2;
    int vox = (v0 << 12) | (v1 << 6) | v2;
    unsigned int pos = atomicAdd(&g_cnt[vox], 1u);
    if (pos < GP_CAP)
        g_bucket[(size_t)vox * GP_CAP + pos] = i;
}

// ---- kernel 2: warp-per-voxel gather max, branch-free batched loads --------
__global__ void gp_gather(const float2* __restrict__ feats,
                          float2*       __restrict__ out) {
    int vox  = (int)((blockIdx.x * (long long)blockDim.x + threadIdx.x) >> 5);
    int lane = threadIdx.x & 31;
    if (vox >= GP_NVOX) return;

    int m = (int)g_cnt[vox];                        // warp-uniform broadcast load
    if (m > GP_CAP) m = GP_CAP;

    if (m == 0) {                                   // empty voxel -> zeros
        float2 z; z.x = 0.0f; z.y = 0.0f;
        out[(size_t)vox * 32 + lane] = z;
        return;
    }

    // one coalesced 128B load pulls all bucket entries into lanes
    // (lanes >= m read slot m-1; value unused but in-bounds)
    int slot  = (lane < m) ? lane : (m - 1);
    int myidx = g_bucket[(size_t)vox * GP_CAP + slot];

    int mm1 = m - 1;

    // straight-line: 8 shfls then 8 independent loads (clamped source lane;
    // k >= m reloads the same address -> L1tex pending-sector merge, no branch)
    float2 f[GP_MLP];
    #pragma unroll
    for (int k = 0; k < GP_MLP; ++k) {
        int src = (k < mm1) ? k : mm1;
        int p = __shfl_sync(0xFFFFFFFFu, myidx, src);
        f[k] = feats[(size_t)p * 32 + lane];        // coalesced 256B per point
    }

    float2 acc = f[0];
    #pragma unroll
    for (int k = 1; k < GP_MLP; ++k) {
        acc.x = fmaxf(acc.x, f[k].x);
        acc.y = fmaxf(acc.y, f[k].y);
    }

    // rare tail (P(cnt>8) ~ 1.5%)
    for (int j = GP_MLP; j < m; ++j) {
        int p = __shfl_sync(0xFFFFFFFFu, myidx, j);
        float2 t = feats[(size_t)p * 32 + lane];
        acc.x = fmaxf(acc.x, t.x);
        acc.y = fmaxf(acc.y, t.y);
    }

    out[(size_t)vox * 32 + lane] = acc;             // coalesced 256B per voxel
}

extern "C" void kernel_launch(void* const* d_in, const int* in_sizes, int n_in,
                              void* d_out, int out_size) {
    const int*    verts = (const int*)d_in[0];      // [N,3] int32
    const float2* feats = (const float2*)d_in[1];   // [N,64] f32 viewed as [N,32] f2
    float2*       out   = (float2*)d_out;           // [NVOX*64] f32 viewed as f2

    int n_pts = in_sizes[0] / 3;                    // 1,000,000

    const int T = 256;

    // 0) zero counters
    gp_zero_cnt<<<GP_NVOX / T, T>>>();

    // 1) build buckets: thread per point
    gp_build<<<(n_pts + T - 1) / T, T>>>(verts, n_pts);

    // 2) gather: warp per voxel
    long long total_threads = (long long)GP_NVOX * 32;
    gp_gather<<<(int)((total_threads + T - 1) / T), T>>>(feats, out);
}

// round 6
// speedup vs baseline: 1.5867x; 1.0329x over previous
#include <cuda_runtime.h>
#include <stdint.h>
#include <math_constants.h>

// GraphPoolOut: voxel max-pool (bucket + gather v3)
//   vertices: [N=1e6, 3] int32, values in [0,256)
//   features: [N, 64] float32
//   out: [64^3, 64] float32 flat; empty voxels -> 0
//
// R5 -> R6: (1) predicated loads via inline PTX (exactly min(m,8) LDGs, no
// dups, no BSSY), (2) cnt+bucket loaded in parallel (chain shortened by one
// L2 latency), (3) counter zeroing folded into gather epilogue (zero kernel
// deleted; also shifts ncu -s 5 onto gather).

#define GP_GRID   64
#define GP_NVOX   (GP_GRID * GP_GRID * GP_GRID)   // 262144
#define GP_C      64
#define GP_CAP    32   // max points per voxel (Poisson(3.81): P(>31) ~ 1e-12)
#define GP_MLP    8    // predicated batched loads; P(cnt>8) ~ 1.5%

// scratch (static device memory; zero-initialized at module load)
__device__ unsigned int g_cnt[GP_NVOX];             // 1 MB
__device__ int          g_bucket[GP_NVOX * GP_CAP]; // 32 MB

// predicated float2 global load: returns (-inf,-inf) when !cond, no branch
__device__ __forceinline__ float2 ldg_f2_pred(const float2* p, int cond) {
    float2 v;
    v.x = -CUDART_INF_F;
    v.y = -CUDART_INF_F;
    asm("{\n\t"
        ".reg .pred p;\n\t"
        "setp.ne.s32 p, %2, 0;\n\t"
        "@p ld.global.nc.v2.f32 {%0, %1}, [%3];\n\t"
        "}"
        : "+f"(v.x), "+f"(v.y)
        : "r"(cond), "l"(p));
    return v;
}

// ---- kernel 1: build per-voxel buckets ------------------------------------
__global__ void gp_build(const int* __restrict__ verts, int n_pts) {
    int i = blockIdx.x * blockDim.x + threadIdx.x;
    if (i >= n_pts) return;
    int v0 = verts[3 * i + 0] >> 2;                 // coords in [0,256): >>2 == //4
    int v1 = verts[3 * i + 1] >> 2;
    int v2 = verts[3 * i + 2] >> 2;
    int vox = (v0 << 12) | (v1 << 6) | v2;
    unsigned int pos = atomicAdd(&g_cnt[vox], 1u);
    if (pos < GP_CAP)
        g_bucket[(size_t)vox * GP_CAP + pos] = i;
}

// ---- kernel 2: warp-per-voxel gather max ----------------------------------
__global__ void gp_gather(const float2* __restrict__ feats,
                          float2*       __restrict__ out) {
    int vox  = (int)((blockIdx.x * (long long)blockDim.x + threadIdx.x) >> 5);
    int lane = threadIdx.x & 31;
    if (vox >= GP_NVOX) return;

    // two INDEPENDENT loads, issued back-to-back (both L2-resident from build):
    // lanes >= m read stale-but-bounded ints; only used in predicated-off math.
    int myidx = g_bucket[(size_t)vox * GP_CAP + lane];
    int m = (int)g_cnt[vox];                        // warp-uniform broadcast
    if (m > GP_CAP) m = GP_CAP;

    // straight-line: 8 shfls + up to 8 predicated independent loads
    float2 f[GP_MLP];
    #pragma unroll
    for (int k = 0; k < GP_MLP; ++k) {
        int p = __shfl_sync(0xFFFFFFFFu, myidx, k); // lane k (valid iff k < m)
        f[k] = ldg_f2_pred(feats + (size_t)p * 32 + lane, k < m);
    }

    float2 acc = f[0];
    #pragma unroll
    for (int k = 1; k < GP_MLP; ++k) {
        acc.x = fmaxf(acc.x, f[k].x);
        acc.y = fmaxf(acc.y, f[k].y);
    }

    // rare tail (P(cnt>8) ~ 1.5%)
    for (int j = GP_MLP; j < m; ++j) {
        int p = __shfl_sync(0xFFFFFFFFu, myidx, j);
        float2 t = feats[(size_t)p * 32 + lane];
        acc.x = fmaxf(acc.x, t.x);
        acc.y = fmaxf(acc.y, t.y);
    }

    // branchless empty-voxel -> zeros (acc is -inf when m==0)
    acc.x = (m == 0) ? 0.0f : acc.x;
    acc.y = (m == 0) ? 0.0f : acc.y;
    out[(size_t)vox * 32 + lane] = acc;             // coalesced 256B per voxel

    // re-zero counter for the next launch (predicated single store)
    if (lane == 0)
        g_cnt[vox] = 0u;
}

extern "C" void kernel_launch(void* const* d_in, const int* in_sizes, int n_in,
                              void* d_out, int out_size) {
    const int*    verts = (const int*)d_in[0];      // [N,3] int32
    const float2* feats = (const float2*)d_in[1];   // [N,64] f32 viewed as [N,32] f2
    float2*       out   = (float2*)d_out;           // [NVOX*64] f32 viewed as f2

    int n_pts = in_sizes[0] / 3;                    // 1,000,000

    const int T = 256;

    // 1) build buckets: thread per point (g_cnt is zero on entry: static init
    //    on first call, re-zeroed by gp_gather on every call)
    gp_build<<<(n_pts + T - 1) / T, T>>>(verts, n_pts);

    // 2) gather: warp per voxel (also re-zeroes g_cnt)
    long long total_threads = (long long)GP_NVOX * 32;
    gp_gather<<<(int)((total_threads + T - 1) / T), T>>>(feats, out);
}

// round 7
// speedup vs baseline: 1.9693x; 1.2412x over previous
#include <cuda_runtime.h>
#include <stdint.h>
#include <math_constants.h>

// GraphPoolOut: voxel max-pool (bucket + gather v4: 2 voxels/warp, float4 lanes)
//   vertices: [N=1e6, 3] int32, values in [0,256)
//   features: [N, 64] float32
//   out: [64^3, 64] float32 flat; empty voxels -> 0
//
// R6 profile: gather DRAM=52.9%, latency-limited (74KB in flight/SM).
// v4 doubles bytes in flight: warp = 2 adjacent voxels, half-warp each;
// 16 lanes x float4 = full 256B feature row per point per half-warp, so one
// LDG.128 slot moves 512B. 8 slots = 4KB in flight/warp. Store = 512B
// contiguous per warp. Build does 2 points/thread (atomic MLP=2).

#define GP_GRID   64
#define GP_NVOX   (GP_GRID * GP_GRID * GP_GRID)   // 262144
#define GP_C      64
#define GP_CAP    32   // max points per voxel (Poisson(3.81): P(>31) ~ 1e-12)
#define GP_MLP    8    // batched point slots per voxel; P(cnt>8) ~ 1.5%

// scratch (static device memory; zero-initialized at module load,
// g_cnt re-zeroed by gp_gather each launch)
__device__ unsigned int g_cnt[GP_NVOX];             // 1 MB
__device__ int          g_bucket[GP_NVOX * GP_CAP]; // 32 MB

// predicated float4 global load: (-inf x4) when !cond, no branch
__device__ __forceinline__ float4 ldg_f4_pred(const float4* p, int cond) {
    float4 v;
    v.x = -CUDART_INF_F; v.y = -CUDART_INF_F;
    v.z = -CUDART_INF_F; v.w = -CUDART_INF_F;
    asm("{\n\t"
        ".reg .pred p;\n\t"
        "setp.ne.s32 p, %4, 0;\n\t"
        "@p ld.global.nc.v4.f32 {%0, %1, %2, %3}, [%5];\n\t"
        "}"
        : "+f"(v.x), "+f"(v.y), "+f"(v.z), "+f"(v.w)
        : "r"(cond), "l"(p));
    return v;
}

__device__ __forceinline__ float4 fmax4(float4 a, float4 b) {
    a.x = fmaxf(a.x, b.x); a.y = fmaxf(a.y, b.y);
    a.z = fmaxf(a.z, b.z); a.w = fmaxf(a.w, b.w);
    return a;
}

// ---- kernel 1: build per-voxel buckets (2 points per thread) ---------------
__global__ void gp_build(const int* __restrict__ verts, int n_pts) {
    int t  = blockIdx.x * blockDim.x + threadIdx.x;
    int i0 = 2 * t;
    if (i0 >= n_pts) return;
    bool two = (i0 + 1) < n_pts;

    // thread reads 6 consecutive ints (warp: fully contiguous 768B)
    int a0 = verts[3 * i0 + 0], a1 = verts[3 * i0 + 1], a2 = verts[3 * i0 + 2];
    int b0 = 0, b1 = 0, b2 = 0;
    if (two) { b0 = verts[3 * i0 + 3]; b1 = verts[3 * i0 + 4]; b2 = verts[3 * i0 + 5]; }

    int vox0 = ((a0 >> 2) << 12) | ((a1 >> 2) << 6) | (a2 >> 2);
    int vox1 = ((b0 >> 2) << 12) | ((b1 >> 2) << 6) | (b2 >> 2);

    // both atomics issued before dependent stores (MLP=2 on the ATOMG chain)
    unsigned int p0 = atomicAdd(&g_cnt[vox0], 1u);
    unsigned int p1 = two ? atomicAdd(&g_cnt[vox1], 1u) : 0xFFFFFFFFu;

    if (p0 < GP_CAP) g_bucket[(size_t)vox0 * GP_CAP + p0] = i0;
    if (p1 < GP_CAP) g_bucket[(size_t)vox1 * GP_CAP + p1] = i0 + 1;
}

// ---- kernel 2: gather max, 2 voxels per warp, float4 lanes ------------------
__global__ void __launch_bounds__(256)
gp_gather(const float4* __restrict__ feats4,   // [N, 16] float4
          float4*       __restrict__ out4) {   // [NVOX, 16] float4
    long long gtid = blockIdx.x * (long long)blockDim.x + threadIdx.x;
    int warp = (int)(gtid >> 5);
    int lane = threadIdx.x & 31;
    int va   = 2 * warp;                        // this warp: voxels va, va+1
    if (va >= GP_NVOX) return;

    int h     = lane >> 4;                      // half-warp id: voxel va+h
    int c     = lane & 15;                      // float4 channel group
    int myvox = va + h;
    int laneh = lane & 16;                      // base lane of my half

    // bucket entries 0..15 of my half's voxel (coalesced 2x64B)
    int myidx = g_bucket[(size_t)myvox * GP_CAP + c];

    // counts (independent broadcast loads, issued in parallel with bucket)
    int ma = (int)g_cnt[va];
    int mb = (int)g_cnt[va + 1];
    ma = min(ma, GP_CAP);
    mb = min(mb, GP_CAP);
    int mh = h ? mb : ma;

    // 8 straight-line slots: slot k = point k of BOTH voxels (512B per LDG.128)
    float4 f[GP_MLP];
    #pragma unroll
    for (int k = 0; k < GP_MLP; ++k) {
        int p = __shfl_sync(0xFFFFFFFFu, myidx, laneh + k);
        f[k] = ldg_f4_pred(feats4 + (size_t)p * 16 + c, k < mh);
    }

    float4 acc = f[0];
    #pragma unroll
    for (int k = 1; k < GP_MLP; ++k)
        acc = fmax4(acc, f[k]);

    // converged tail to max(ma, mb); per-half predication keeps shfl legal
    int mmax = max(ma, mb);
    for (int j = GP_MLP; j < mmax; ++j) {
        int p;
        if (j < 16)                             // uniform branch (j warp-uniform)
            p = __shfl_sync(0xFFFFFFFFu, myidx, laneh + j);
        else                                    // P ~ 1e-7: read bucket directly
            p = g_bucket[(size_t)myvox * GP_CAP + j];
        float4 t = ldg_f4_pred(feats4 + (size_t)p * 16 + c, j < mh);
        acc = fmax4(acc, t);
    }

    // empty voxel -> zeros (acc is -inf when mh==0)
    if (mh == 0) { acc.x = 0.0f; acc.y = 0.0f; acc.z = 0.0f; acc.w = 0.0f; }

    // full warp writes 512B contiguous (two adjacent 256B voxel rows)
    out4[(size_t)myvox * 16 + c] = acc;

    // re-zero counters for next launch (lane 0 -> va, lane 16 -> va+1)
    if (c == 0)
        g_cnt[myvox] = 0u;
}

extern "C" void kernel_launch(void* const* d_in, const int* in_sizes, int n_in,
                              void* d_out, int out_size) {
    const int*    verts  = (const int*)d_in[0];    // [N,3] int32
    const float4* feats4 = (const float4*)d_in[1]; // [N,64] f32 viewed as [N,16] f4
    float4*       out4   = (float4*)d_out;         // [NVOX,16] f4

    int n_pts = in_sizes[0] / 3;                   // 1,000,000

    const int T = 256;

    // 1) build buckets: 2 points per thread
    int n_thr = (n_pts + 1) / 2;
    gp_build<<<(n_thr + T - 1) / T, T>>>(verts, n_pts);

    // 2) gather: 2 voxels per warp (also re-zeroes g_cnt)
    long long total_threads = (long long)(GP_NVOX / 2) * 32;
    gp_gather<<<(int)((total_threads + T - 1) / T), T>>>(feats4, out4);
}